// round 1
// baseline (speedup 1.0000x reference)
#include <cuda_runtime.h>
#include <math.h>

// Problem constants
#define Bb 2
#define Ss 4096
#define Dd 2048
#define Mm (Bb*Ss)   // 8192 rows

// ---------------------------------------------------------------------------
// Scratch (device globals; no allocation allowed)
// ---------------------------------------------------------------------------
static __device__ float g_r[(size_t)Mm*Dd];   // silu(x@Wr)
static __device__ float g_f[(size_t)Mm*Dd];   // sigmoid(x@Wf); later reused as gated g
static __device__ float g_c[(size_t)Mm*Dd];   // silu(x@Wc)
static __device__ float g_h[(size_t)Mm*Dd];   // scan output
// Tree levels 1..12 of the Brent-Kung scan, (f,c) pairs. Total B*D*(S-1) float2.
static __device__ float2 g_lev[(size_t)Bb*Dd*(Ss-1)];

// ---------------------------------------------------------------------------
// Activation helper
// ---------------------------------------------------------------------------
__device__ __forceinline__ float actf(float v, int act) {
    if (act == 0) return v;
    float s = 1.0f / (1.0f + expf(-v));
    return (act == 2) ? s : v * s;   // 2: sigmoid, 1: silu
}

// The (non-associative) combine from the reference: a = prefix, b = element.
__device__ __forceinline__ float2 comb(float2 a, float2 b) {
    return make_float2(a.x * b.x, b.x * a.y + (1.0f - b.x) * b.y);
}

// ---------------------------------------------------------------------------
// SGEMM: Out[M,N] = act(A[M,K] @ W[K,N]).  BM=BN=128, BK=8, 256 thr, 8x8/thr.
// ---------------------------------------------------------------------------
__global__ __launch_bounds__(256, 2)
void sgemm_act(const float* __restrict__ A, const float* __restrict__ Bw,
               float* __restrict__ Out, int act, int M, int N, int K)
{
    const int BM = 128, BN = 128, BK = 8;
    __shared__ __align__(16) float As[2][BK][BM];
    __shared__ __align__(16) float Bs[2][BK][BN];

    int tid = threadIdx.x;
    int tx = tid & 15, ty = tid >> 4;
    int m0 = blockIdx.y * BM, n0 = blockIdx.x * BN;

    int arow = tid >> 1;           // 0..127
    int acol = (tid & 1) * 4;      // 0 or 4
    int brow = tid >> 5;           // 0..7
    int bcol = (tid & 31) * 4;     // 0..124

    const float* Aptr = A + (size_t)(m0 + arow) * K + acol;
    const float* Bptr = Bw + (size_t)brow * N + n0 + bcol;

    float acc[8][8];
    #pragma unroll
    for (int i = 0; i < 8; i++)
        #pragma unroll
        for (int j = 0; j < 8; j++) acc[i][j] = 0.0f;

    // Preload tile 0
    float4 pa = *(const float4*)Aptr;
    float4 pb = *(const float4*)Bptr;
    As[0][acol + 0][arow] = pa.x;
    As[0][acol + 1][arow] = pa.y;
    As[0][acol + 2][arow] = pa.z;
    As[0][acol + 3][arow] = pa.w;
    *(float4*)&Bs[0][brow][bcol] = pb;
    __syncthreads();

    int nt = K / BK;
    int cur = 0;
    for (int t = 0; t < nt; t++) {
        if (t + 1 < nt) {
            pa = *(const float4*)(Aptr + (t + 1) * BK);
            pb = *(const float4*)(Bptr + (size_t)(t + 1) * BK * N);
        }
        #pragma unroll
        for (int kk = 0; kk < BK; kk++) {
            float4 a0 = *(const float4*)&As[cur][kk][ty * 4];
            float4 a1 = *(const float4*)&As[cur][kk][64 + ty * 4];
            float4 b0 = *(const float4*)&Bs[cur][kk][tx * 4];
            float4 b1 = *(const float4*)&Bs[cur][kk][64 + tx * 4];
            float av[8] = {a0.x, a0.y, a0.z, a0.w, a1.x, a1.y, a1.z, a1.w};
            float bv[8] = {b0.x, b0.y, b0.z, b0.w, b1.x, b1.y, b1.z, b1.w};
            #pragma unroll
            for (int i = 0; i < 8; i++)
                #pragma unroll
                for (int j = 0; j < 8; j++)
                    acc[i][j] = fmaf(av[i], bv[j], acc[i][j]);
        }
        if (t + 1 < nt) {
            int nxt = cur ^ 1;
            As[nxt][acol + 0][arow] = pa.x;
            As[nxt][acol + 1][arow] = pa.y;
            As[nxt][acol + 2][arow] = pa.z;
            As[nxt][acol + 3][arow] = pa.w;
            *(float4*)&Bs[nxt][brow][bcol] = pb;
        }
        __syncthreads();
        cur ^= 1;
    }

    // Epilogue
    #pragma unroll
    for (int i = 0; i < 8; i++) {
        int m = m0 + ((i < 4) ? (ty * 4 + i) : (64 + ty * 4 + (i - 4)));
        #pragma unroll
        for (int jh = 0; jh < 2; jh++) {
            int n = n0 + jh * 64 + tx * 4;
            float4 v;
            v.x = actf(acc[i][jh * 4 + 0], act);
            v.y = actf(acc[i][jh * 4 + 1], act);
            v.z = actf(acc[i][jh * 4 + 2], act);
            v.w = actf(acc[i][jh * 4 + 3], act);
            *(float4*)&Out[(size_t)m * N + n] = v;
        }
    }
}

// ---------------------------------------------------------------------------
// Scan kernels — replicate jax.lax.associative_scan's recursion EXACTLY
// (combine is not associative, so the tree bracketing matters).
// ---------------------------------------------------------------------------

// Level 1 up-sweep: E1[b,j,d] = comb((f,c)[2j], (f,c)[2j+1])
__global__ void scan_up1(const float* __restrict__ f, const float* __restrict__ c,
                         float2* __restrict__ out)
{
    int i = blockIdx.x * blockDim.x + threadIdx.x;
    const int n = Bb * (Ss / 2) * Dd;
    if (i >= n) return;
    int d = i % Dd;
    int t = i / Dd;
    int j = t % (Ss / 2);
    int b = t / (Ss / 2);
    int i0 = (b * Ss + 2 * j) * Dd + d;
    float2 ea = make_float2(f[i0], c[i0]);
    float2 eb = make_float2(f[i0 + Dd], c[i0 + Dd]);
    out[i] = comb(ea, eb);
}

// Generic up-sweep (level l>=2): out has seq-len halfS; in has 2*halfS.
__global__ void scan_up(const float2* __restrict__ in, float2* __restrict__ out,
                        int halfS, int n)
{
    int i = blockIdx.x * blockDim.x + threadIdx.x;
    if (i >= n) return;
    int d = i % Dd;
    int t = i / Dd;
    int j = t % halfS;
    int b = t / halfS;
    int i0 = (b * (2 * halfS) + 2 * j) * Dd + d;
    out[i] = comb(in[i0], in[i0 + Dd]);
}

// Down-sweep level l (1..11), in-place over E_l: R[0]=E[0]; R[2m+1]=Rnext[m];
// R[2m+2]=comb(Rnext[m], E[2m+2]).
__global__ void scan_down(float2* __restrict__ cur, const float2* __restrict__ nxt,
                          int Sl, int n)
{
    int i = blockIdx.x * blockDim.x + threadIdx.x;
    if (i >= n) return;
    int d = i % Dd;
    int t = i / Dd;
    int k = t % Sl;
    int b = t / Sl;
    if (k == 0) return;
    int Snext = Sl >> 1;
    if (k & 1) {
        cur[i] = nxt[(b * Snext + (k >> 1)) * Dd + d];
    } else {
        float2 a = nxt[(b * Snext + (k >> 1) - 1) * Dd + d];
        cur[i] = comb(a, cur[i]);
    }
}

// Down-sweep level 0: produce h (c-component only).
__global__ void scan_down0(const float* __restrict__ f, const float* __restrict__ c,
                           const float2* __restrict__ r1, float* __restrict__ h)
{
    int i = blockIdx.x * blockDim.x + threadIdx.x;
    const int n = Mm * Dd;
    if (i >= n) return;
    int d = i % Dd;
    int t = i / Dd;
    int s = t % Ss;
    int b = t / Ss;
    float hv;
    if (s == 0) {
        hv = c[i];
    } else if (s & 1) {
        hv = r1[(b * (Ss / 2) + (s >> 1)) * Dd + d].y;
    } else {
        float2 a = r1[(b * (Ss / 2) + (s >> 1) - 1) * Dd + d];
        float fb = f[i], cb = c[i];
        hv = fb * a.y + (1.0f - fb) * cb;
    }
    h[i] = hv;
}

// ---------------------------------------------------------------------------
// RMSNorm + gate: g = r * (h * rsqrt(mean(h^2)+eps)) * ln_scale, one block/row.
// ---------------------------------------------------------------------------
__global__ void norm_gate(const float* __restrict__ h, const float* __restrict__ r,
                          const float* __restrict__ sc, float* __restrict__ g)
{
    __shared__ float red[8];
    int row = blockIdx.x;
    int tid = threadIdx.x;  // 256 threads, 8 elems each
    const float* hp = h + (size_t)row * Dd;

    float4 h0 = *(const float4*)&hp[tid * 4];
    float4 h1 = *(const float4*)&hp[1024 + tid * 4];
    float ss = h0.x * h0.x + h0.y * h0.y + h0.z * h0.z + h0.w * h0.w
             + h1.x * h1.x + h1.y * h1.y + h1.z * h1.z + h1.w * h1.w;
    #pragma unroll
    for (int o = 16; o; o >>= 1) ss += __shfl_xor_sync(0xffffffffu, ss, o);
    if ((tid & 31) == 0) red[tid >> 5] = ss;
    __syncthreads();
    if (tid < 32) {
        float v = (tid < 8) ? red[tid] : 0.0f;
        #pragma unroll
        for (int o = 4; o; o >>= 1) v += __shfl_xor_sync(0xffffffffu, v, o);
        if (tid == 0) red[0] = v;
    }
    __syncthreads();
    float rms = rsqrtf(red[0] * (1.0f / Dd) + 1e-5f);

    const float* rp = r + (size_t)row * Dd;
    float* gp = g + (size_t)row * Dd;
    float4 r0 = *(const float4*)&rp[tid * 4];
    float4 r1 = *(const float4*)&rp[1024 + tid * 4];
    float4 s0 = *(const float4*)&sc[tid * 4];
    float4 s1 = *(const float4*)&sc[1024 + tid * 4];
    float4 o0, o1;
    o0.x = r0.x * (h0.x * rms) * s0.x;
    o0.y = r0.y * (h0.y * rms) * s0.y;
    o0.z = r0.z * (h0.z * rms) * s0.z;
    o0.w = r0.w * (h0.w * rms) * s0.w;
    o1.x = r1.x * (h1.x * rms) * s1.x;
    o1.y = r1.y * (h1.y * rms) * s1.y;
    o1.z = r1.z * (h1.z * rms) * s1.z;
    o1.w = r1.w * (h1.w * rms) * s1.w;
    *(float4*)&gp[tid * 4] = o0;
    *(float4*)&gp[1024 + tid * 4] = o1;
}

// ---------------------------------------------------------------------------
// Host launcher
// ---------------------------------------------------------------------------
extern "C" void kernel_launch(void* const* d_in, const int* in_sizes, int n_in,
                              void* d_out, int out_size)
{
    const float* x  = (const float*)d_in[0];
    const float* Wr = (const float*)d_in[1];
    const float* Wf = (const float*)d_in[2];
    const float* Wc = (const float*)d_in[3];
    const float* Wo = (const float*)d_in[4];
    const float* ln = (const float*)d_in[5];
    float* out = (float*)d_out;

    float *r, *f, *c, *h;
    float2* lev;
    cudaGetSymbolAddress((void**)&r, g_r);
    cudaGetSymbolAddress((void**)&f, g_f);
    cudaGetSymbolAddress((void**)&c, g_c);
    cudaGetSymbolAddress((void**)&h, g_h);
    cudaGetSymbolAddress((void**)&lev, g_lev);

    dim3 gg(Dd / 128, Mm / 128);  // (16, 64)
    sgemm_act<<<gg, 256>>>(x, Wr, r, 1, Mm, Dd, Dd);  // silu
    sgemm_act<<<gg, 256>>>(x, Wf, f, 2, Mm, Dd, Dd);  // sigmoid
    sgemm_act<<<gg, 256>>>(x, Wc, c, 1, Mm, Dd, Dd);  // silu

    // Level offsets in g_lev (levels 1..12)
    size_t off[14];
    off[1] = 0;
    for (int l = 1; l <= 12; l++) {
        size_t nl = (size_t)Bb * (Ss >> l) * Dd;
        off[l + 1] = off[l] + nl;
    }

    {
        int n = Bb * (Ss / 2) * Dd;
        scan_up1<<<(n + 255) / 256, 256>>>(f, c, lev + off[1]);
    }
    for (int l = 2; l <= 12; l++) {
        int n = Bb * (Ss >> l) * Dd;
        scan_up<<<(n + 255) / 256, 256>>>(lev + off[l - 1], lev + off[l], Ss >> l, n);
    }
    for (int l = 11; l >= 1; l--) {
        int n = Bb * (Ss >> l) * Dd;
        scan_down<<<(n + 255) / 256, 256>>>(lev + off[l], lev + off[l + 1], Ss >> l, n);
    }
    {
        int n = Mm * Dd;
        scan_down0<<<(n + 255) / 256, 256>>>(f, c, lev + off[1], h);
    }

    norm_gate<<<Mm, 256>>>(h, r, ln, f);              // g reuses g_f
    sgemm_act<<<gg, 256>>>(f, Wo, out, 0, Mm, Dd, Dd);
}

// round 10
// speedup vs baseline: 1.6873x; 1.6873x over previous
#include <cuda_runtime.h>
#include <cuda_bf16.h>
#include <math.h>
#include <stdint.h>

#define Bb 2
#define Ss 4096
#define Dd 2048
#define Mm (Bb*Ss)   // 8192

// ---------------------------------------------------------------------------
// Scratch (device globals; allocation is forbidden)
// ---------------------------------------------------------------------------
static __device__ float g_r[(size_t)Mm*Dd];
static __device__ float g_f[(size_t)Mm*Dd];
static __device__ float g_c[(size_t)Mm*Dd];
static __device__ float g_h[(size_t)Mm*Dd];
static __device__ float2 g_lev[(size_t)Bb*Dd*(Ss-1)];
static __device__ __nv_bfloat16 g_xh[(size_t)Mm*Dd];   // x hi; later gate hi
static __device__ __nv_bfloat16 g_xl[(size_t)Mm*Dd];   // x lo; later gate lo
static __device__ __nv_bfloat16 g_wh[(size_t)Dd*Dd];   // W^T hi (reused per GEMM)
static __device__ __nv_bfloat16 g_wl[(size_t)Dd*Dd];   // W^T lo

// ---------------------------------------------------------------------------
// PTX helpers (sm_80-era only: cp.async, ldmatrix, mma.sync — no tcgen05)
// ---------------------------------------------------------------------------
__device__ __forceinline__ uint32_t smem_u32(const void* p) {
    uint32_t a;
    asm("{ .reg .u64 t; cvta.to.shared.u64 t, %1; cvt.u32.u64 %0, t; }"
        : "=r"(a) : "l"(p));
    return a;
}

#define CP16(dst, src) \
    asm volatile("cp.async.cg.shared.global [%0], [%1], 16;" :: "r"(dst), "l"(src))
#define CP_COMMIT() asm volatile("cp.async.commit_group;" ::: "memory")

__device__ __forceinline__ void ldsm4(uint32_t* r, uint32_t addr) {
    asm volatile("ldmatrix.sync.aligned.m8n8.x4.shared.b16 {%0,%1,%2,%3}, [%4];"
        : "=r"(r[0]), "=r"(r[1]), "=r"(r[2]), "=r"(r[3]) : "r"(addr));
}

__device__ __forceinline__ void mma16816(float* d, const uint32_t* a,
                                         uint32_t b0, uint32_t b1) {
    asm volatile(
        "mma.sync.aligned.m16n8k16.row.col.f32.bf16.bf16.f32 "
        "{%0,%1,%2,%3}, {%4,%5,%6,%7}, {%8,%9}, {%0,%1,%2,%3};"
        : "+f"(d[0]), "+f"(d[1]), "+f"(d[2]), "+f"(d[3])
        : "r"(a[0]), "r"(a[1]), "r"(a[2]), "r"(a[3]), "r"(b0), "r"(b1));
}

__device__ __forceinline__ uint32_t sw128(uint32_t off) {
    return off ^ ((off >> 3) & 0x70);
}

__device__ __forceinline__ float actf(float v, int act) {
    if (act == 0) return v;
    float s = 1.0f / (1.0f + expf(-v));
    return (act == 2) ? s : v * s;
}

// ---------------------------------------------------------------------------
// HMMA GEMM: Out[M,N=2048] = act(A @ B^T), A=(Ah+Al)[M,K] bf16, Bt=(Bh+Bl)[N,K]
// bf16, K=2048. 3-product split accumulated in fp32 registers.
// CTA tile 128x128, BK=64, 3-stage cp.async, 8 warps (4m x 2n), warp 32x64.
// ---------------------------------------------------------------------------
#define NCHUNK 32
#define STG_BYTES 65536
#define OFF_AH 0
#define OFF_AL 16384
#define OFF_BH 32768
#define OFF_BL 49152
#define SMEM_TOTAL (3*STG_BYTES)

__global__ __launch_bounds__(256, 1)
void gemm_mma(const __nv_bfloat16* __restrict__ Ah, const __nv_bfloat16* __restrict__ Al,
              const __nv_bfloat16* __restrict__ Bh, const __nv_bfloat16* __restrict__ Bl,
              float* __restrict__ Out, int act)
{
    extern __shared__ __align__(1024) char smem[];
    uint32_t sb = smem_u32(smem);
    int tid = threadIdx.x, lane = tid & 31, wid = tid >> 5;
    int m0 = blockIdx.y * 128, n0 = blockIdx.x * 128;
    int wm = wid & 3, wn = wid >> 2;      // warp grid 4m x 2n
    int l16 = lane & 15, lseg = lane >> 4;

    // --- cp.async loader mapping: row = tid>>1 (0..127), 4 x 16B vectors ---
    int lrow = tid >> 1;
    int lcb = (tid & 1) * 64;
    const char* pAh = (const char*)(Ah + (size_t)(m0 + lrow) * Dd) + lcb;
    const char* pAl = (const char*)(Al + (size_t)(m0 + lrow) * Dd) + lcb;
    const char* pBh = (const char*)(Bh + (size_t)(n0 + lrow) * Dd) + lcb;
    const char* pBl = (const char*)(Bl + (size_t)(n0 + lrow) * Dd) + lcb;
    uint32_t swo[4];
    #pragma unroll
    for (int v = 0; v < 4; v++) swo[v] = sw128(lrow * 128 + lcb + v * 16);

    auto load_stage = [&](int chunk, int s) {
        uint32_t base = sb + s * STG_BYTES;
        size_t go = (size_t)chunk * 128;  // 64 bf16 = 128 bytes per chunk
        #pragma unroll
        for (int v = 0; v < 4; v++) {
            CP16(base + OFF_AH + swo[v], pAh + go + v * 16);
            CP16(base + OFF_AL + swo[v], pAl + go + v * 16);
            CP16(base + OFF_BH + swo[v], pBh + go + v * 16);
            CP16(base + OFF_BL + swo[v], pBl + go + v * 16);
        }
        CP_COMMIT();
    };

    // --- ldmatrix swizzled offsets, precomputed for all 4 k-steps ---
    // A (m16 x k16 tile): lanes 0-15 rows, lanes 16-31 same rows at +16B in k.
    // B (n16 x k16): lanes 0-15 n-rows, lanes 16-31 at +16B in k. No .trans
    // needed: Bt is [N,K] K-contiguous, n-major rows give the .col fragment.
    uint32_t a_sw[2][4], b_sw[4][4];
    #pragma unroll
    for (int mt = 0; mt < 2; mt++) {
        uint32_t base = (uint32_t)(wm * 32 + mt * 16 + l16) * 128 + lseg * 16;
        #pragma unroll
        for (int kk = 0; kk < 4; kk++) a_sw[mt][kk] = sw128(base + kk * 32);
    }
    #pragma unroll
    for (int p = 0; p < 4; p++) {
        uint32_t base = (uint32_t)(wn * 64 + p * 16 + l16) * 128 + lseg * 16;
        #pragma unroll
        for (int kk = 0; kk < 4; kk++) b_sw[p][kk] = sw128(base + kk * 32);
    }

    float acc[2][8][4];
    #pragma unroll
    for (int mt = 0; mt < 2; mt++)
        #pragma unroll
        for (int nt = 0; nt < 8; nt++)
            #pragma unroll
            for (int q = 0; q < 4; q++) acc[mt][nt][q] = 0.0f;

    load_stage(0, 0);
    load_stage(1, 1);
    load_stage(2, 2);

    for (int t = 0; t < NCHUNK; t++) {
        int s = t % 3;
        int rem = (NCHUNK - 1) - t;
        if (rem >= 2)      asm volatile("cp.async.wait_group 2;" ::: "memory");
        else if (rem == 1) asm volatile("cp.async.wait_group 1;" ::: "memory");
        else               asm volatile("cp.async.wait_group 0;" ::: "memory");
        __syncthreads();

        uint32_t st = sb + s * STG_BYTES;
        #pragma unroll
        for (int kk = 0; kk < 4; kk++) {
            uint32_t ah[2][4], al[2][4], bh[4][4], bl[4][4];
            #pragma unroll
            for (int mt = 0; mt < 2; mt++) {
                ldsm4(ah[mt], st + OFF_AH + a_sw[mt][kk]);
                ldsm4(al[mt], st + OFF_AL + a_sw[mt][kk]);
            }
            #pragma unroll
            for (int p = 0; p < 4; p++) {
                ldsm4(bh[p], st + OFF_BH + b_sw[p][kk]);
                ldsm4(bl[p], st + OFF_BL + b_sw[p][kk]);
            }
            #pragma unroll
            for (int mt = 0; mt < 2; mt++) {
                #pragma unroll
                for (int p = 0; p < 4; p++) {
                    // x4 matrices: {r0,r2} = ntile 2p, {r1,r3} = ntile 2p+1
                    mma16816(acc[mt][2 * p],     ah[mt], bh[p][0], bh[p][2]);
                    mma16816(acc[mt][2 * p + 1], ah[mt], bh[p][1], bh[p][3]);
                    mma16816(acc[mt][2 * p],     ah[mt], bl[p][0], bl[p][2]);
                    mma16816(acc[mt][2 * p + 1], ah[mt], bl[p][1], bl[p][3]);
                    mma16816(acc[mt][2 * p],     al[mt], bh[p][0], bh[p][2]);
                    mma16816(acc[mt][2 * p + 1], al[mt], bh[p][1], bh[p][3]);
                }
            }
        }
        __syncthreads();
        if (t + 3 < NCHUNK) load_stage(t + 3, s);
    }

    // --- Epilogue: fp32 accum -> act -> gmem ---
    int g = lane >> 2, t4 = lane & 3;
    #pragma unroll
    for (int mt = 0; mt < 2; mt++) {
        int r0 = m0 + wm * 32 + mt * 16 + g;
        #pragma unroll
        for (int nt = 0; nt < 8; nt++) {
            int col = n0 + wn * 64 + nt * 8 + t4 * 2;
            float2 v0, v1;
            v0.x = actf(acc[mt][nt][0], act);
            v0.y = actf(acc[mt][nt][1], act);
            v1.x = actf(acc[mt][nt][2], act);
            v1.y = actf(acc[mt][nt][3], act);
            *(float2*)&Out[(size_t)r0 * Dd + col] = v0;
            *(float2*)&Out[(size_t)(r0 + 8) * Dd + col] = v1;
        }
    }
}

// ---------------------------------------------------------------------------
// W [K,N] fp32 -> Wt hi/lo [N,K] bf16 (transpose + split)
// ---------------------------------------------------------------------------
__global__ void transpose_split(const float* __restrict__ W,
                                __nv_bfloat16* __restrict__ Th,
                                __nv_bfloat16* __restrict__ Tl)
{
    __shared__ float t[32][33];
    int n0 = blockIdx.x * 32, k0 = blockIdx.y * 32;
    int tx = threadIdx.x, ty = threadIdx.y;  // 32 x 8
    #pragma unroll
    for (int i = 0; i < 4; i++)
        t[ty + i * 8][tx] = W[(size_t)(k0 + ty + i * 8) * Dd + n0 + tx];
    __syncthreads();
    #pragma unroll
    for (int i = 0; i < 4; i++) {
        float v = t[tx][ty + i * 8];
        __nv_bfloat16 hi = __float2bfloat16(v);
        __nv_bfloat16 lo = __float2bfloat16(v - __bfloat162float(hi));
        size_t idx = (size_t)(n0 + ty + i * 8) * Dd + k0 + tx;
        Th[idx] = hi;
        Tl[idx] = lo;
    }
}

// x fp32 -> xh, xl bf16
__global__ void convert_x(const float4* __restrict__ x,
                          __nv_bfloat162* __restrict__ xh,
                          __nv_bfloat162* __restrict__ xl)
{
    int i = blockIdx.x * blockDim.x + threadIdx.x;
    if (i >= Mm * Dd / 4) return;
    float4 v = x[i];
    __nv_bfloat16 h0 = __float2bfloat16(v.x), h1 = __float2bfloat16(v.y);
    __nv_bfloat16 h2 = __float2bfloat16(v.z), h3 = __float2bfloat16(v.w);
    __nv_bfloat16 l0 = __float2bfloat16(v.x - __bfloat162float(h0));
    __nv_bfloat16 l1 = __float2bfloat16(v.y - __bfloat162float(h1));
    __nv_bfloat16 l2 = __float2bfloat16(v.z - __bfloat162float(h2));
    __nv_bfloat16 l3 = __float2bfloat16(v.w - __bfloat162float(h3));
    xh[2 * i]     = __halves2bfloat162(h0, h1);
    xh[2 * i + 1] = __halves2bfloat162(h2, h3);
    xl[2 * i]     = __halves2bfloat162(l0, l1);
    xl[2 * i + 1] = __halves2bfloat162(l2, l3);
}

// ---------------------------------------------------------------------------
// Scan kernels — exact replication of jax.lax.associative_scan's tree
// (combine is non-associative; bracketing matters).
// ---------------------------------------------------------------------------
__device__ __forceinline__ float2 comb(float2 a, float2 b) {
    return make_float2(a.x * b.x, b.x * a.y + (1.0f - b.x) * b.y);
}

__global__ void scan_up1(const float* __restrict__ f, const float* __restrict__ c,
                         float2* __restrict__ out)
{
    int i = blockIdx.x * blockDim.x + threadIdx.x;
    const int n = Bb * (Ss / 2) * Dd;
    if (i >= n) return;
    int d = i % Dd;
    int t = i / Dd;
    int j = t % (Ss / 2);
    int b = t / (Ss / 2);
    int i0 = (b * Ss + 2 * j) * Dd + d;
    float2 ea = make_float2(f[i0], c[i0]);
    float2 eb = make_float2(f[i0 + Dd], c[i0 + Dd]);
    out[i] = comb(ea, eb);
}

__global__ void scan_up(const float2* __restrict__ in, float2* __restrict__ out,
                        int halfS, int n)
{
    int i = blockIdx.x * blockDim.x + threadIdx.x;
    if (i >= n) return;
    int d = i % Dd;
    int t = i / Dd;
    int j = t % halfS;
    int b = t / halfS;
    int i0 = (b * (2 * halfS) + 2 * j) * Dd + d;
    out[i] = comb(in[i0], in[i0 + Dd]);
}

__global__ void scan_down(float2* __restrict__ cur, const float2* __restrict__ nxt,
                          int Sl, int n)
{
    int i = blockIdx.x * blockDim.x + threadIdx.x;
    if (i >= n) return;
    int d = i % Dd;
    int t = i / Dd;
    int k = t % Sl;
    int b = t / Sl;
    if (k == 0) return;
    int Snext = Sl >> 1;
    if (k & 1) {
        cur[i] = nxt[(b * Snext + (k >> 1)) * Dd + d];
    } else {
        float2 a = nxt[(b * Snext + (k >> 1) - 1) * Dd + d];
        cur[i] = comb(a, cur[i]);
    }
}

__global__ void scan_down0(const float* __restrict__ f, const float* __restrict__ c,
                           const float2* __restrict__ r1, float* __restrict__ h)
{
    int i = blockIdx.x * blockDim.x + threadIdx.x;
    const int n = Mm * Dd;
    if (i >= n) return;
    int d = i % Dd;
    int t = i / Dd;
    int s = t % Ss;
    int b = t / Ss;
    float hv;
    if (s == 0) {
        hv = c[i];
    } else if (s & 1) {
        hv = r1[(b * (Ss / 2) + (s >> 1)) * Dd + d].y;
    } else {
        float2 a = r1[(b * (Ss / 2) + (s >> 1) - 1) * Dd + d];
        float fb = f[i], cb = c[i];
        hv = fb * a.y + (1.0f - fb) * cb;
    }
    h[i] = hv;
}

// ---------------------------------------------------------------------------
// RMSNorm + gate -> bf16 hi/lo (for the Wo GEMM)
// ---------------------------------------------------------------------------
__global__ void norm_gate(const float* __restrict__ h, const float* __restrict__ r,
                          const float* __restrict__ sc,
                          __nv_bfloat16* __restrict__ gh, __nv_bfloat16* __restrict__ gl)
{
    __shared__ float red[8];
    int row = blockIdx.x;
    int tid = threadIdx.x;
    const float* hp = h + (size_t)row * Dd;

    float4 h0 = *(const float4*)&hp[tid * 4];
    float4 h1 = *(const float4*)&hp[1024 + tid * 4];
    float ss = h0.x * h0.x + h0.y * h0.y + h0.z * h0.z + h0.w * h0.w
             + h1.x * h1.x + h1.y * h1.y + h1.z * h1.z + h1.w * h1.w;
    #pragma unroll
    for (int o = 16; o; o >>= 1) ss += __shfl_xor_sync(0xffffffffu, ss, o);
    if ((tid & 31) == 0) red[tid >> 5] = ss;
    __syncthreads();
    if (tid < 32) {
        float v = (tid < 8) ? red[tid] : 0.0f;
        #pragma unroll
        for (int o = 4; o; o >>= 1) v += __shfl_xor_sync(0xffffffffu, v, o);
        if (tid == 0) red[0] = v;
    }
    __syncthreads();
    float rms = rsqrtf(red[0] * (1.0f / Dd) + 1e-5f);

    const float* rp = r + (size_t)row * Dd;
    float4 r0 = *(const float4*)&rp[tid * 4];
    float4 r1 = *(const float4*)&rp[1024 + tid * 4];
    float4 s0 = *(const float4*)&sc[tid * 4];
    float4 s1 = *(const float4*)&sc[1024 + tid * 4];

    float o0[8];
    o0[0] = r0.x * (h0.x * rms) * s0.x;
    o0[1] = r0.y * (h0.y * rms) * s0.y;
    o0[2] = r0.z * (h0.z * rms) * s0.z;
    o0[3] = r0.w * (h0.w * rms) * s0.w;
    o0[4] = r1.x * (h1.x * rms) * s1.x;
    o0[5] = r1.y * (h1.y * rms) * s1.y;
    o0[6] = r1.z * (h1.z * rms) * s1.z;
    o0[7] = r1.w * (h1.w * rms) * s1.w;

    __nv_bfloat16 hh[8], ll[8];
    #pragma unroll
    for (int k = 0; k < 8; k++) {
        hh[k] = __float2bfloat16(o0[k]);
        ll[k] = __float2bfloat16(o0[k] - __bfloat162float(hh[k]));
    }
    size_t base0 = (size_t)row * Dd + tid * 4;
    size_t base1 = base0 + 1024;
    __nv_bfloat162* gh2 = (__nv_bfloat162*)gh;
    __nv_bfloat162* gl2 = (__nv_bfloat162*)gl;
    gh2[base0 / 2]     = __halves2bfloat162(hh[0], hh[1]);
    gh2[base0 / 2 + 1] = __halves2bfloat162(hh[2], hh[3]);
    gh2[base1 / 2]     = __halves2bfloat162(hh[4], hh[5]);
    gh2[base1 / 2 + 1] = __halves2bfloat162(hh[6], hh[7]);
    gl2[base0 / 2]     = __halves2bfloat162(ll[0], ll[1]);
    gl2[base0 / 2 + 1] = __halves2bfloat162(ll[2], ll[3]);
    gl2[base1 / 2]     = __halves2bfloat162(ll[4], ll[5]);
    gl2[base1 / 2 + 1] = __halves2bfloat162(ll[6], ll[7]);
}

// ---------------------------------------------------------------------------
// Host launcher
// ---------------------------------------------------------------------------
extern "C" void kernel_launch(void* const* d_in, const int* in_sizes, int n_in,
                              void* d_out, int out_size)
{
    const float* x  = (const float*)d_in[0];
    const float* Wr = (const float*)d_in[1];
    const float* Wf = (const float*)d_in[2];
    const float* Wc = (const float*)d_in[3];
    const float* Wo = (const float*)d_in[4];
    const float* ln = (const float*)d_in[5];
    float* out = (float*)d_out;

    float *r, *f, *c, *h;
    float2* lev;
    __nv_bfloat16 *xh, *xl, *wh, *wl;
    cudaGetSymbolAddress((void**)&r, g_r);
    cudaGetSymbolAddress((void**)&f, g_f);
    cudaGetSymbolAddress((void**)&c, g_c);
    cudaGetSymbolAddress((void**)&h, g_h);
    cudaGetSymbolAddress((void**)&lev, g_lev);
    cudaGetSymbolAddress((void**)&xh, g_xh);
    cudaGetSymbolAddress((void**)&xl, g_xl);
    cudaGetSymbolAddress((void**)&wh, g_wh);
    cudaGetSymbolAddress((void**)&wl, g_wl);

    cudaFuncSetAttribute(gemm_mma, cudaFuncAttributeMaxDynamicSharedMemorySize, SMEM_TOTAL);

    dim3 tg(Dd / 32, Dd / 32), tb(32, 8);
    dim3 gg(Dd / 128, Mm / 128);  // (16, 64)

    convert_x<<<(Mm * Dd / 4 + 255) / 256, 256>>>((const float4*)x,
                                                  (__nv_bfloat162*)xh, (__nv_bfloat162*)xl);

    transpose_split<<<tg, tb>>>(Wr, wh, wl);
    gemm_mma<<<gg, 256, SMEM_TOTAL>>>(xh, xl, wh, wl, r, 1);   // silu
    transpose_split<<<tg, tb>>>(Wf, wh, wl);
    gemm_mma<<<gg, 256, SMEM_TOTAL>>>(xh, xl, wh, wl, f, 2);   // sigmoid
    transpose_split<<<tg, tb>>>(Wc, wh, wl);
    gemm_mma<<<gg, 256, SMEM_TOTAL>>>(xh, xl, wh, wl, c, 1);   // silu

    // Scan (exact jax tree)
    size_t off[14];
    off[1] = 0;
    for (int l = 1; l <= 12; l++) {
        size_t nl = (size_t)Bb * (Ss >> l) * Dd;
        off[l + 1] = off[l] + nl;
    }
    {
        int n = Bb * (Ss / 2) * Dd;
        scan_up1<<<(n + 255) / 256, 256>>>(f, c, lev + off[1]);
    }
    for (int l = 2; l <= 12; l++) {
        int n = Bb * (Ss >> l) * Dd;
        scan_up<<<(n + 255) / 256, 256>>>(lev + off[l - 1], lev + off[l], Ss >> l, n);
    }
    for (int l = 11; l >= 1; l--) {
        int n = Bb * (Ss >> l) * Dd;
        scan_down<<<(n + 255) / 256, 256>>>(lev + off[l], lev + off[l + 1], Ss >> l, n);
    }
    {
        int n = Mm * Dd;
        scan_down0<<<(n + 255) / 256, 256>>>(f, c, lev + off[1], h);
    }

    // RMSNorm + gate -> bf16 pair (reuses xh/xl storage)
    norm_gate<<<Mm, 256>>>(h, r, ln, xh, xl);

    // Output projection
    transpose_split<<<tg, tb>>>(Wo, wh, wl);
    gemm_mma<<<gg, 256, SMEM_TOTAL>>>(xh, xl, wh, wl, out, 0);
}

// round 11
// speedup vs baseline: 2.0293x; 1.2027x over previous
#include <cuda_runtime.h>
#include <cuda_bf16.h>
#include <math.h>
#include <stdint.h>

#define Bb 2
#define Ss 4096
#define Dd 2048
#define Mm (Bb*Ss)   // 8192

// ---------------------------------------------------------------------------
// Scratch (device globals; allocation is forbidden)
// ---------------------------------------------------------------------------
static __device__ float g_r[(size_t)Mm*Dd];
static __device__ float g_f[(size_t)Mm*Dd];
static __device__ float g_c[(size_t)Mm*Dd];
static __device__ float2 g_lev[(size_t)Bb*Dd*(Ss-1)];
static __device__ __nv_bfloat16 g_xh[(size_t)Mm*Dd];   // x hi; later gate hi
static __device__ __nv_bfloat16 g_xl[(size_t)Mm*Dd];   // x lo; later gate lo
static __device__ __nv_bfloat16 g_wh[(size_t)Dd*Dd];   // W^T hi (reused per GEMM)
static __device__ __nv_bfloat16 g_wl[(size_t)Dd*Dd];   // W^T lo

// ---------------------------------------------------------------------------
// PTX helpers (sm_80-era only: cp.async, ldmatrix, mma.sync — no tcgen05)
// ---------------------------------------------------------------------------
__device__ __forceinline__ uint32_t smem_u32(const void* p) {
    uint32_t a;
    asm("{ .reg .u64 t; cvta.to.shared.u64 t, %1; cvt.u32.u64 %0, t; }"
        : "=r"(a) : "l"(p));
    return a;
}

#define CP16(dst, src) \
    asm volatile("cp.async.cg.shared.global [%0], [%1], 16;" :: "r"(dst), "l"(src))
#define CP_COMMIT() asm volatile("cp.async.commit_group;" ::: "memory")

__device__ __forceinline__ void ldsm4(uint32_t* r, uint32_t addr) {
    asm volatile("ldmatrix.sync.aligned.m8n8.x4.shared.b16 {%0,%1,%2,%3}, [%4];"
        : "=r"(r[0]), "=r"(r[1]), "=r"(r[2]), "=r"(r[3]) : "r"(addr));
}

__device__ __forceinline__ void mma16816(float* d, const uint32_t* a,
                                         uint32_t b0, uint32_t b1) {
    asm volatile(
        "mma.sync.aligned.m16n8k16.row.col.f32.bf16.bf16.f32 "
        "{%0,%1,%2,%3}, {%4,%5,%6,%7}, {%8,%9}, {%0,%1,%2,%3};"
        : "+f"(d[0]), "+f"(d[1]), "+f"(d[2]), "+f"(d[3])
        : "r"(a[0]), "r"(a[1]), "r"(a[2]), "r"(a[3]), "r"(b0), "r"(b1));
}

__device__ __forceinline__ uint32_t sw128(uint32_t off) {
    return off ^ ((off >> 3) & 0x70);
}

__device__ __forceinline__ float actf(float v, int act) {
    if (act == 0) return v;
    float s = 1.0f / (1.0f + expf(-v));
    return (act == 2) ? s : v * s;
}

// ---------------------------------------------------------------------------
// HMMA GEMM: Out[M,N=2048] = act(A @ B^T), A=(Ah+Al)[M,K] bf16, Bt=(Bh+Bl)[N,K]
// bf16, K=2048. 3-product split accumulated in fp32 registers.
// CTA tile 128x128, BK=64, 3-stage cp.async, 16 warps (4m x 4n), warp 32x32.
// One __syncthreads per chunk; loads for t+2 issued before compute of t.
// ---------------------------------------------------------------------------
#define NCHUNK 32
#define STG_BYTES 65536
#define OFF_AH 0
#define OFF_AL 16384
#define OFF_BH 32768
#define OFF_BL 49152
#define SMEM_TOTAL (3*STG_BYTES)

__global__ __launch_bounds__(512, 1)
void gemm_mma(const __nv_bfloat16* __restrict__ Ah, const __nv_bfloat16* __restrict__ Al,
              const __nv_bfloat16* __restrict__ Bh, const __nv_bfloat16* __restrict__ Bl,
              float* __restrict__ Out, int act)
{
    extern __shared__ __align__(1024) char smem[];
    uint32_t sb = smem_u32(smem);
    int tid = threadIdx.x, lane = tid & 31, wid = tid >> 5;
    int m0 = blockIdx.y * 128, n0 = blockIdx.x * 128;
    int wm = wid & 3, wn = wid >> 2;      // warp grid 4m x 4n
    int l16 = lane & 15, lseg = lane >> 4;

    // --- cp.async loader mapping: row = tid>>2 (0..127), 2 x 16B vectors ---
    int lrow = tid >> 2;
    int lcb = (tid & 3) * 32;
    const char* pAh = (const char*)(Ah + (size_t)(m0 + lrow) * Dd) + lcb;
    const char* pAl = (const char*)(Al + (size_t)(m0 + lrow) * Dd) + lcb;
    const char* pBh = (const char*)(Bh + (size_t)(n0 + lrow) * Dd) + lcb;
    const char* pBl = (const char*)(Bl + (size_t)(n0 + lrow) * Dd) + lcb;
    uint32_t swo[2];
    swo[0] = sw128(lrow * 128 + lcb);
    swo[1] = sw128(lrow * 128 + lcb + 16);

    auto load_stage = [&](int chunk, int s) {
        uint32_t base = sb + s * STG_BYTES;
        size_t go = (size_t)chunk * 128;  // 64 bf16 = 128 bytes per chunk
        #pragma unroll
        for (int v = 0; v < 2; v++) {
            CP16(base + OFF_AH + swo[v], pAh + go + v * 16);
            CP16(base + OFF_AL + swo[v], pAl + go + v * 16);
            CP16(base + OFF_BH + swo[v], pBh + go + v * 16);
            CP16(base + OFF_BL + swo[v], pBl + go + v * 16);
        }
        CP_COMMIT();
    };

    // --- ldmatrix swizzled offsets for all 4 k-steps ---
    // A (m16 x k16): lanes 0-15 rows, lanes 16-31 same rows at +16B in k.
    // B (n16 x k16): n-major rows give the .col fragment directly (no .trans).
    uint32_t a_sw[2][4], b_sw[2][4];
    #pragma unroll
    for (int mt = 0; mt < 2; mt++) {
        uint32_t base = (uint32_t)(wm * 32 + mt * 16 + l16) * 128 + lseg * 16;
        #pragma unroll
        for (int kk = 0; kk < 4; kk++) a_sw[mt][kk] = sw128(base + kk * 32);
    }
    #pragma unroll
    for (int p = 0; p < 2; p++) {
        uint32_t base = (uint32_t)(wn * 32 + p * 16 + l16) * 128 + lseg * 16;
        #pragma unroll
        for (int kk = 0; kk < 4; kk++) b_sw[p][kk] = sw128(base + kk * 32);
    }

    float acc[2][4][4];
    #pragma unroll
    for (int mt = 0; mt < 2; mt++)
        #pragma unroll
        for (int nt = 0; nt < 4; nt++)
            #pragma unroll
            for (int q = 0; q < 4; q++) acc[mt][nt][q] = 0.0f;

    load_stage(0, 0);
    load_stage(1, 1);

    for (int t = 0; t < NCHUNK; t++) {
        if (t == NCHUNK - 1) asm volatile("cp.async.wait_group 0;" ::: "memory");
        else                 asm volatile("cp.async.wait_group 1;" ::: "memory");
        __syncthreads();

        // Issue loads for chunk t+2 into the buffer consumed at t-1 (freed by
        // this iteration's barrier): (t+2)%3 == (t-1)%3.
        if (t + 2 < NCHUNK) load_stage(t + 2, (t + 2) % 3);

        uint32_t st = sb + (t % 3) * STG_BYTES;
        #pragma unroll
        for (int kk = 0; kk < 4; kk++) {
            uint32_t ah[2][4], al[2][4], bh[2][4], bl[2][4];
            #pragma unroll
            for (int mt = 0; mt < 2; mt++) {
                ldsm4(ah[mt], st + OFF_AH + a_sw[mt][kk]);
                ldsm4(al[mt], st + OFF_AL + a_sw[mt][kk]);
            }
            #pragma unroll
            for (int p = 0; p < 2; p++) {
                ldsm4(bh[p], st + OFF_BH + b_sw[p][kk]);
                ldsm4(bl[p], st + OFF_BL + b_sw[p][kk]);
            }
            #pragma unroll
            for (int mt = 0; mt < 2; mt++) {
                #pragma unroll
                for (int p = 0; p < 2; p++) {
                    // x4 matrices: {r0,r2} = ntile 2p, {r1,r3} = ntile 2p+1
                    mma16816(acc[mt][2 * p],     ah[mt], bh[p][0], bh[p][2]);
                    mma16816(acc[mt][2 * p + 1], ah[mt], bh[p][1], bh[p][3]);
                    mma16816(acc[mt][2 * p],     ah[mt], bl[p][0], bl[p][2]);
                    mma16816(acc[mt][2 * p + 1], ah[mt], bl[p][1], bl[p][3]);
                    mma16816(acc[mt][2 * p],     al[mt], bh[p][0], bh[p][2]);
                    mma16816(acc[mt][2 * p + 1], al[mt], bh[p][1], bh[p][3]);
                }
            }
        }
    }

    // --- Epilogue: fp32 accum -> act -> gmem ---
    int g = lane >> 2, t4 = lane & 3;
    #pragma unroll
    for (int mt = 0; mt < 2; mt++) {
        int r0 = m0 + wm * 32 + mt * 16 + g;
        #pragma unroll
        for (int nt = 0; nt < 4; nt++) {
            int col = n0 + wn * 32 + nt * 8 + t4 * 2;
            float2 v0, v1;
            v0.x = actf(acc[mt][nt][0], act);
            v0.y = actf(acc[mt][nt][1], act);
            v1.x = actf(acc[mt][nt][2], act);
            v1.y = actf(acc[mt][nt][3], act);
            *(float2*)&Out[(size_t)r0 * Dd + col] = v0;
            *(float2*)&Out[(size_t)(r0 + 8) * Dd + col] = v1;
        }
    }
}

// ---------------------------------------------------------------------------
// W [K,N] fp32 -> Wt hi/lo [N,K] bf16 (transpose + split)
// ---------------------------------------------------------------------------
__global__ void transpose_split(const float* __restrict__ W,
                                __nv_bfloat16* __restrict__ Th,
                                __nv_bfloat16* __restrict__ Tl)
{
    __shared__ float t[32][33];
    int n0 = blockIdx.x * 32, k0 = blockIdx.y * 32;
    int tx = threadIdx.x, ty = threadIdx.y;  // 32 x 8
    #pragma unroll
    for (int i = 0; i < 4; i++)
        t[ty + i * 8][tx] = W[(size_t)(k0 + ty + i * 8) * Dd + n0 + tx];
    __syncthreads();
    #pragma unroll
    for (int i = 0; i < 4; i++) {
        float v = t[tx][ty + i * 8];
        __nv_bfloat16 hi = __float2bfloat16(v);
        __nv_bfloat16 lo = __float2bfloat16(v - __bfloat162float(hi));
        size_t idx = (size_t)(n0 + ty + i * 8) * Dd + k0 + tx;
        Th[idx] = hi;
        Tl[idx] = lo;
    }
}

// x fp32 -> xh, xl bf16
__global__ void convert_x(const float4* __restrict__ x,
                          __nv_bfloat162* __restrict__ xh,
                          __nv_bfloat162* __restrict__ xl)
{
    int i = blockIdx.x * blockDim.x + threadIdx.x;
    if (i >= Mm * Dd / 4) return;
    float4 v = x[i];
    __nv_bfloat16 h0 = __float2bfloat16(v.x), h1 = __float2bfloat16(v.y);
    __nv_bfloat16 h2 = __float2bfloat16(v.z), h3 = __float2bfloat16(v.w);
    __nv_bfloat16 l0 = __float2bfloat16(v.x - __bfloat162float(h0));
    __nv_bfloat16 l1 = __float2bfloat16(v.y - __bfloat162float(h1));
    __nv_bfloat16 l2 = __float2bfloat16(v.z - __bfloat162float(h2));
    __nv_bfloat16 l3 = __float2bfloat16(v.w - __bfloat162float(h3));
    xh[2 * i]     = __halves2bfloat162(h0, h1);
    xh[2 * i + 1] = __halves2bfloat162(h2, h3);
    xl[2 * i]     = __halves2bfloat162(l0, l1);
    xl[2 * i + 1] = __halves2bfloat162(l2, l3);
}

// ---------------------------------------------------------------------------
// Scan kernels — exact replication of jax.lax.associative_scan's tree
// (combine is non-associative; bracketing matters).
// ---------------------------------------------------------------------------
__device__ __forceinline__ float2 comb(float2 a, float2 b) {
    return make_float2(a.x * b.x, b.x * a.y + (1.0f - b.x) * b.y);
}

__global__ void scan_up1(const float* __restrict__ f, const float* __restrict__ c,
                         float2* __restrict__ out)
{
    int i = blockIdx.x * blockDim.x + threadIdx.x;
    const int n = Bb * (Ss / 2) * Dd;
    if (i >= n) return;
    int d = i % Dd;
    int t = i / Dd;
    int j = t % (Ss / 2);
    int b = t / (Ss / 2);
    int i0 = (b * Ss + 2 * j) * Dd + d;
    float2 ea = make_float2(f[i0], c[i0]);
    float2 eb = make_float2(f[i0 + Dd], c[i0 + Dd]);
    out[i] = comb(ea, eb);
}

__global__ void scan_up(const float2* __restrict__ in, float2* __restrict__ out,
                        int halfS, int n)
{
    int i = blockIdx.x * blockDim.x + threadIdx.x;
    if (i >= n) return;
    int d = i % Dd;
    int t = i / Dd;
    int j = t % halfS;
    int b = t / halfS;
    int i0 = (b * (2 * halfS) + 2 * j) * Dd + d;
    out[i] = comb(in[i0], in[i0 + Dd]);
}

__global__ void scan_down(float2* __restrict__ cur, const float2* __restrict__ nxt,
                          int Sl, int n)
{
    int i = blockIdx.x * blockDim.x + threadIdx.x;
    if (i >= n) return;
    int d = i % Dd;
    int t = i / Dd;
    int k = t % Sl;
    int b = t / Sl;
    if (k == 0) return;
    int Snext = Sl >> 1;
    if (k & 1) {
        cur[i] = nxt[(b * Snext + (k >> 1)) * Dd + d];
    } else {
        float2 a = nxt[(b * Snext + (k >> 1) - 1) * Dd + d];
        cur[i] = comb(a, cur[i]);
    }
}

// ---------------------------------------------------------------------------
// Fused: scan level-0 down-sweep + RMSNorm + gate -> bf16 hi/lo.
// One block per (b,s) row; the s-branch is block-uniform (no divergence).
// ---------------------------------------------------------------------------
__global__ void scan_norm_gate(const float* __restrict__ f, const float* __restrict__ c,
                               const float2* __restrict__ r1,
                               const float* __restrict__ r, const float* __restrict__ sc,
                               __nv_bfloat16* __restrict__ gh, __nv_bfloat16* __restrict__ gl)
{
    __shared__ float red[8];
    int row = blockIdx.x;
    int tid = threadIdx.x;           // 256 threads, 8 elems each
    int b = row / Ss, s = row % Ss;
    size_t base = (size_t)row * Dd;

    int dIdx[8];
    #pragma unroll
    for (int k = 0; k < 8; k++)
        dIdx[k] = (k < 4) ? (tid * 4 + k) : (1024 + tid * 4 + (k - 4));

    float hv[8];
    if (s == 0) {
        #pragma unroll
        for (int k = 0; k < 8; k++) hv[k] = c[base + dIdx[k]];
    } else if (s & 1) {
        size_t rbase = (size_t)(b * (Ss / 2) + (s >> 1)) * Dd;
        #pragma unroll
        for (int k = 0; k < 8; k++) hv[k] = r1[rbase + dIdx[k]].y;
    } else {
        size_t rbase = (size_t)(b * (Ss / 2) + (s >> 1) - 1) * Dd;
        #pragma unroll
        for (int k = 0; k < 8; k++) {
            float2 a = r1[rbase + dIdx[k]];
            float fb = f[base + dIdx[k]], cb = c[base + dIdx[k]];
            hv[k] = fb * a.y + (1.0f - fb) * cb;
        }
    }

    float ss = 0.0f;
    #pragma unroll
    for (int k = 0; k < 8; k++) ss += hv[k] * hv[k];
    #pragma unroll
    for (int o = 16; o; o >>= 1) ss += __shfl_xor_sync(0xffffffffu, ss, o);
    if ((tid & 31) == 0) red[tid >> 5] = ss;
    __syncthreads();
    if (tid < 32) {
        float v = (tid < 8) ? red[tid] : 0.0f;
        #pragma unroll
        for (int o = 4; o; o >>= 1) v += __shfl_xor_sync(0xffffffffu, v, o);
        if (tid == 0) red[0] = v;
    }
    __syncthreads();
    float rms = rsqrtf(red[0] * (1.0f / Dd) + 1e-5f);

    #pragma unroll
    for (int k = 0; k < 8; k++) {
        float o = r[base + dIdx[k]] * (hv[k] * rms) * sc[dIdx[k]];
        __nv_bfloat16 hi = __float2bfloat16(o);
        __nv_bfloat16 lo = __float2bfloat16(o - __bfloat162float(hi));
        gh[base + dIdx[k]] = hi;
        gl[base + dIdx[k]] = lo;
    }
}

// ---------------------------------------------------------------------------
// Host launcher
// ---------------------------------------------------------------------------
extern "C" void kernel_launch(void* const* d_in, const int* in_sizes, int n_in,
                              void* d_out, int out_size)
{
    const float* x  = (const float*)d_in[0];
    const float* Wr = (const float*)d_in[1];
    const float* Wf = (const float*)d_in[2];
    const float* Wc = (const float*)d_in[3];
    const float* Wo = (const float*)d_in[4];
    const float* ln = (const float*)d_in[5];
    float* out = (float*)d_out;

    float *r, *f, *c;
    float2* lev;
    __nv_bfloat16 *xh, *xl, *wh, *wl;
    cudaGetSymbolAddress((void**)&r, g_r);
    cudaGetSymbolAddress((void**)&f, g_f);
    cudaGetSymbolAddress((void**)&c, g_c);
    cudaGetSymbolAddress((void**)&lev, g_lev);
    cudaGetSymbolAddress((void**)&xh, g_xh);
    cudaGetSymbolAddress((void**)&xl, g_xl);
    cudaGetSymbolAddress((void**)&wh, g_wh);
    cudaGetSymbolAddress((void**)&wl, g_wl);

    cudaFuncSetAttribute(gemm_mma, cudaFuncAttributeMaxDynamicSharedMemorySize, SMEM_TOTAL);

    dim3 tg(Dd / 32, Dd / 32), tb(32, 8);
    dim3 gg(Dd / 128, Mm / 128);  // (16, 64)

    convert_x<<<(Mm * Dd / 4 + 255) / 256, 256>>>((const float4*)x,
                                                  (__nv_bfloat162*)xh, (__nv_bfloat162*)xl);

    transpose_split<<<tg, tb>>>(Wr, wh, wl);
    gemm_mma<<<gg, 512, SMEM_TOTAL>>>(xh, xl, wh, wl, r, 1);   // silu
    transpose_split<<<tg, tb>>>(Wf, wh, wl);
    gemm_mma<<<gg, 512, SMEM_TOTAL>>>(xh, xl, wh, wl, f, 2);   // sigmoid
    transpose_split<<<tg, tb>>>(Wc, wh, wl);
    gemm_mma<<<gg, 512, SMEM_TOTAL>>>(xh, xl, wh, wl, c, 1);   // silu

    // Scan (exact jax tree)
    size_t off[14];
    off[1] = 0;
    for (int l = 1; l <= 12; l++) {
        size_t nl = (size_t)Bb * (Ss >> l) * Dd;
        off[l + 1] = off[l] + nl;
    }
    {
        int n = Bb * (Ss / 2) * Dd;
        scan_up1<<<(n + 255) / 256, 256>>>(f, c, lev + off[1]);
    }
    for (int l = 2; l <= 12; l++) {
        int n = Bb * (Ss >> l) * Dd;
        scan_up<<<(n + 255) / 256, 256>>>(lev + off[l - 1], lev + off[l], Ss >> l, n);
    }
    for (int l = 11; l >= 1; l--) {
        int n = Bb * (Ss >> l) * Dd;
        scan_down<<<(n + 255) / 256, 256>>>(lev + off[l], lev + off[l + 1], Ss >> l, n);
    }

    // Fused level-0 down-sweep + RMSNorm + gate -> bf16 pair (reuses xh/xl)
    scan_norm_gate<<<Mm, 256>>>(f, c, lev + off[1], r, ln, xh, xl);

    // Output projection
    transpose_split<<<tg, tb>>>(Wo, wh, wl);
    gemm_mma<<<gg, 512, SMEM_TOTAL>>>(xh, xl, wh, wl, out, 0);
}